// round 1
// baseline (speedup 1.0000x reference)
#include <cuda_runtime.h>
#include <cuda_bf16.h>
#include <cstdint>
#include <cstddef>

// Problem constants
#define N_TOK 8192
#define H_DIM 1024
#define V_DIM 32000

constexpr int BM = 128;
constexpr int BN = 256;
constexpr int BK = 32;
constexpr int KT = H_DIM / BK;  // 32 k-iterations

// Scratch (no cudaMalloc allowed)
__device__ __nv_bfloat16 g_xb[(size_t)N_TOK * H_DIM];      // 16 MB
__device__ __nv_bfloat16 g_wb[(size_t)V_DIM * H_DIM];      // 64 MB
__device__ float g_S[N_TOK];    // sum of exp(logits) per row
__device__ float g_T[N_TOK];    // target logit per row
__device__ int   g_tgt[N_TOK];  // normalized int32 targets

// ---------------------------------------------------------------------------
// f32 -> bf16 conversion kernels (also zero the exp-sum accumulator)
// ---------------------------------------------------------------------------
__global__ void convert_x_kernel(const float* __restrict__ x) {
    int i = blockIdx.x * blockDim.x + threadIdx.x;  // float4 index
    float4 v = reinterpret_cast<const float4*>(x)[i];
    unsigned short b0 = __bfloat16_as_ushort(__float2bfloat16(v.x));
    unsigned short b1 = __bfloat16_as_ushort(__float2bfloat16(v.y));
    unsigned short b2 = __bfloat16_as_ushort(__float2bfloat16(v.z));
    unsigned short b3 = __bfloat16_as_ushort(__float2bfloat16(v.w));
    uint32_t u0 = ((uint32_t)b1 << 16) | b0;
    uint32_t u1 = ((uint32_t)b3 << 16) | b2;
    reinterpret_cast<uint2*>(g_xb)[i] = make_uint2(u0, u1);
    if (i < N_TOK) g_S[i] = 0.0f;
}

__global__ void convert_w_kernel(const float* __restrict__ w) {
    int i = blockIdx.x * blockDim.x + threadIdx.x;
    float4 v = reinterpret_cast<const float4*>(w)[i];
    unsigned short b0 = __bfloat16_as_ushort(__float2bfloat16(v.x));
    unsigned short b1 = __bfloat16_as_ushort(__float2bfloat16(v.y));
    unsigned short b2 = __bfloat16_as_ushort(__float2bfloat16(v.z));
    unsigned short b3 = __bfloat16_as_ushort(__float2bfloat16(v.w));
    uint32_t u0 = ((uint32_t)b1 << 16) | b0;
    uint32_t u1 = ((uint32_t)b3 << 16) | b2;
    reinterpret_cast<uint2*>(g_wb)[i] = make_uint2(u0, u1);
}

// ---------------------------------------------------------------------------
// Target dtype sniffing: if the buffer is int64, every odd 32-bit word among
// the first 8192 words is the (zero) high half. If int32, those words are
// actual targets (all-zero probability ~(1/32000)^4096 == never).
// Only reads beyond word 8191 in int64 mode, where the buffer is 16384 words.
// ---------------------------------------------------------------------------
__global__ void prep_targets_kernel(const int* __restrict__ t) {
    __shared__ int nz;
    if (threadIdx.x == 0) nz = 0;
    __syncthreads();
    int local = 0;
    for (int i = threadIdx.x; i < 4096; i += 256) local |= t[2 * i + 1];
    if (local) atomicOr(&nz, 1);
    __syncthreads();
    bool is64 = (nz == 0);
    for (int i = threadIdx.x; i < N_TOK; i += 256)
        g_tgt[i] = is64 ? t[2 * i] : t[i];
}

// ---------------------------------------------------------------------------
// GEMM + fused cross-entropy partial epilogue
// ---------------------------------------------------------------------------
__device__ __forceinline__ void cp16(uint32_t* dst, const void* src) {
    uint32_t d = (uint32_t)__cvta_generic_to_shared(dst);
    asm volatile("cp.async.cg.shared.global [%0], [%1], 16;\n" :: "r"(d), "l"(src));
}

// Swizzled tile layout: per row, 4 chunks of 16B; chunk cc stored at
// position cc ^ ((row>>1)&3). Verified conflict-free for both the
// gmem->smem stores and the mma fragment LDS pattern.
__device__ __forceinline__ void load_tile(uint32_t* As, uint32_t* Bs,
                                          int kt, int buf, int tid,
                                          int mBase, int vBase) {
    uint32_t* Ad = As + buf * 2048;
    const __nv_bfloat16* xrow = g_xb + (size_t)mBase * H_DIM + kt * BK;
#pragma unroll
    for (int p = 0; p < 2; p++) {           // 128 rows * 4 chunks = 512
        int t = tid + p * 256;
        int row = t >> 2, cc = t & 3;
        int dw = row * 16 + ((cc ^ ((row >> 1) & 3)) << 2);
        cp16(Ad + dw, xrow + (size_t)row * H_DIM + cc * 8);
    }
    uint32_t* Bd = Bs + buf * 4096;
    const __nv_bfloat16* wrow = g_wb + (size_t)vBase * H_DIM + kt * BK;
#pragma unroll
    for (int p = 0; p < 4; p++) {           // 256 rows * 4 chunks = 1024
        int t = tid + p * 256;
        int row = t >> 2, cc = t & 3;
        int dw = row * 16 + ((cc ^ ((row >> 1) & 3)) << 2);
        cp16(Bd + dw, wrow + (size_t)row * H_DIM + cc * 8);
    }
}

__global__ void __launch_bounds__(256, 1)
gemm_lce_kernel(const float* __restrict__ bias) {
    extern __shared__ uint32_t smem[];
    uint32_t* As = smem;               // 2 bufs * 2048 words = 16 KB
    uint32_t* Bs = smem + 4096;        // 2 bufs * 4096 words = 32 KB
    float* sBias = (float*)(smem + 12288);   // 256 floats
    int*   sTgt  = (int*)(smem + 12544);     // 128 ints
    float* sRow  = (float*)(smem + 12672);   // 128 floats

    const int tid  = threadIdx.x;
    const int lane = tid & 31;
    const int warp = tid >> 5;
    const int wm   = warp >> 2;   // 0..1  (m warps, 64 rows each)
    const int wn   = warp & 3;    // 0..3  (n warps, 64 cols each)
    const int g    = lane >> 2;   // groupID 0..7
    const int tig  = lane & 3;    // thread-in-group

    const int mBase = blockIdx.y * BM;
    const int vBase = blockIdx.x * BN;

    if (tid < 128) { sRow[tid] = 0.0f; sTgt[tid] = g_tgt[mBase + tid]; }
    sBias[tid] = bias[vBase + tid];

    // Prefetch tile 0
    load_tile(As, Bs, 0, 0, tid, mBase, vBase);
    asm volatile("cp.async.commit_group;\n");

    float acc[4][8][4];
#pragma unroll
    for (int i = 0; i < 4; i++)
#pragma unroll
        for (int j = 0; j < 8; j++)
#pragma unroll
            for (int c = 0; c < 4; c++) acc[i][j][c] = 0.0f;

    const int X = (g >> 1) & 3;             // swizzle xor, constant per thread
    const int raBase = (wm * 64 + g) * 16;  // A row base (words)
    const int rbBase = (wn * 64 + g) * 16;  // B row base (words)

    for (int kt = 0; kt < KT; kt++) {
        if (kt + 1 < KT) load_tile(As, Bs, kt + 1, (kt + 1) & 1, tid, mBase, vBase);
        asm volatile("cp.async.commit_group;\n");
        if (kt + 1 < KT) asm volatile("cp.async.wait_group 1;\n");
        else             asm volatile("cp.async.wait_group 0;\n");
        __syncthreads();

        const uint32_t* Ac = As + (kt & 1) * 2048;
        const uint32_t* Bc = Bs + (kt & 1) * 4096;

#pragma unroll
        for (int ks = 0; ks < 2; ks++) {
            const int off0 = (((ks * 2)     ^ X) << 2) + tig;  // logical word ks*8+tig
            const int off1 = (((ks * 2 + 1) ^ X) << 2) + tig;  // logical word ks*8+4+tig

            uint32_t a[4][4];
#pragma unroll
            for (int i = 0; i < 4; i++) {
                int base = raBase + i * 256;
                a[i][0] = Ac[base +       off0];
                a[i][1] = Ac[base + 128 + off0];
                a[i][2] = Ac[base +       off1];
                a[i][3] = Ac[base + 128 + off1];
            }
#pragma unroll
            for (int j = 0; j < 8; j++) {
                uint32_t b0 = Bc[rbBase + j * 128 + off0];
                uint32_t b1 = Bc[rbBase + j * 128 + off1];
#pragma unroll
                for (int i = 0; i < 4; i++) {
                    asm volatile(
                        "mma.sync.aligned.m16n8k16.row.col.f32.bf16.bf16.f32 "
                        "{%0,%1,%2,%3}, {%4,%5,%6,%7}, {%8,%9}, {%0,%1,%2,%3};\n"
                        : "+f"(acc[i][j][0]), "+f"(acc[i][j][1]),
                          "+f"(acc[i][j][2]), "+f"(acc[i][j][3])
                        : "r"(a[i][0]), "r"(a[i][1]), "r"(a[i][2]), "r"(a[i][3]),
                          "r"(b0), "r"(b1));
                }
            }
        }
        __syncthreads();
    }

    // ---------------- Epilogue: bias, exp, row-sums, target logit ----------
    float rs[4][2];
#pragma unroll
    for (int i = 0; i < 4; i++) { rs[i][0] = 0.0f; rs[i][1] = 0.0f; }

#pragma unroll
    for (int i = 0; i < 4; i++) {
#pragma unroll
        for (int h = 0; h < 2; h++) {
            int lr = wm * 64 + i * 16 + h * 8 + g;
            int tgt = sTgt[lr];
            float s = 0.0f;
#pragma unroll
            for (int j = 0; j < 8; j++) {
                int cl = wn * 64 + j * 8 + tig * 2;
                float v0 = acc[i][j][h * 2 + 0] + sBias[cl];
                float v1 = acc[i][j][h * 2 + 1] + sBias[cl + 1];
                int gc = vBase + cl;
                if (tgt == gc)     g_T[mBase + lr] = v0;
                if (tgt == gc + 1) g_T[mBase + lr] = v1;
                s += __expf(v0) + __expf(v1);
            }
            rs[i][h] = s;
        }
    }
#pragma unroll
    for (int i = 0; i < 4; i++)
#pragma unroll
        for (int h = 0; h < 2; h++) {
            float s = rs[i][h];
            s += __shfl_xor_sync(0xffffffffu, s, 1);
            s += __shfl_xor_sync(0xffffffffu, s, 2);
            if (tig == 0)
                atomicAdd(&sRow[wm * 64 + i * 16 + h * 8 + g], s);
        }
    __syncthreads();
    if (tid < 128) atomicAdd(&g_S[mBase + tid], sRow[tid]);
}

// ---------------------------------------------------------------------------
// Final reduction: loss = mean(log(S) - T)  (all targets valid, count = N)
// ---------------------------------------------------------------------------
__global__ void finalize_kernel(float* __restrict__ out) {
    __shared__ double red[256];
    double a = 0.0;
    for (int i = threadIdx.x; i < N_TOK; i += 256)
        a += (double)(logf(g_S[i]) - g_T[i]);
    red[threadIdx.x] = a;
    __syncthreads();
    for (int s = 128; s > 0; s >>= 1) {
        if (threadIdx.x < s) red[threadIdx.x] += red[threadIdx.x + s];
        __syncthreads();
    }
    if (threadIdx.x == 0) out[0] = (float)(red[0] / (double)N_TOK);
}

// ---------------------------------------------------------------------------
extern "C" void kernel_launch(void* const* d_in, const int* in_sizes, int n_in,
                              void* d_out, int out_size) {
    const float* x    = (const float*)d_in[0];
    const float* w    = (const float*)d_in[1];
    const float* bias = (const float*)d_in[2];
    const int*   tgt  = (const int*)d_in[3];   // int32 view; dtype sniffed on device
    float* out = (float*)d_out;

    cudaFuncSetAttribute(gemm_lce_kernel,
                         cudaFuncAttributeMaxDynamicSharedMemorySize, 51200);

    convert_x_kernel<<<(N_TOK * H_DIM / 4) / 256, 256>>>(x);
    convert_w_kernel<<<((size_t)V_DIM * H_DIM / 4) / 256, 256>>>(w);
    prep_targets_kernel<<<1, 256>>>(tgt);

    dim3 grid(V_DIM / BN, N_TOK / BM);  // (125, 64)
    gemm_lce_kernel<<<grid, 256, 51200>>>(bias);

    finalize_kernel<<<1, 256>>>(out);
}